// round 3
// baseline (speedup 1.0000x reference)
#include <cuda_runtime.h>
#include <math.h>
#include <stdint.h>

// ---------------- problem constants ----------------
#define NBATCH   2
#define SEQLEN   512
#define D_INNER  4096
#define D_STATE  16
#define DT_RANK  128
#define NROWS    (NBATCH * SEQLEN)          // 1024
#define XPC      (DT_RANK + 2 * D_STATE)    // 160 columns of xp
#define KSPLIT   8

// ---------------- scratch (device globals; no allocation allowed) ----------------
__device__ float g_part[KSPLIT * NROWS * XPC];   // GEMM1 split-K partials (5.2 MB)
__device__ float g_xp[NROWS * XPC];              // xp = [dt_in(128) | B(16) | C(16)]
__device__ float g_dt[NROWS * D_INNER];          // softplus(dt) (16.8 MB)

// ---------------- small helpers ----------------
__device__ __forceinline__ float ex2f(float v) {
    float r;
    asm("ex2.approx.ftz.f32 %0, %1;" : "=f"(r) : "f"(v));
    return r;
}

__device__ __forceinline__ float softplusf(float z) {
    // log1p(exp(z)), overflow-safe; matches jax.nn.softplus to ~1e-7
    return fmaxf(z, 0.0f) + log1pf(__expf(-fabsf(z)));
}

__device__ __forceinline__ void cp16(float* dst, const float* src) {
    unsigned s = (unsigned)__cvta_generic_to_shared(dst);
    asm volatile("cp.async.cg.shared.global [%0], [%1], 16;" :: "r"(s), "l"(src));
}
__device__ __forceinline__ void cp_commit() {
    asm volatile("cp.async.commit_group;");
}
template <int N>
__device__ __forceinline__ void cp_wait() {
    asm volatile("cp.async.wait_group %0;" :: "n"(N));
}

// =====================================================================
// GEMM1: xp_part[z][row][c] = sum_{k in slice z} x[row][k] * xpw[c][k]
// grid (16 Mtiles, 2 Ntiles, 8 Ksplits), 256 threads
// Mtile=64, Ntile=80, Kslice=512, KC=16, micro-tile 4x5
// =====================================================================
__global__ __launch_bounds__(256, 1)
void gemm1_kernel(const float* __restrict__ x, const float* __restrict__ w)
{
    __shared__ float As[64][17];   // [row][k]
    __shared__ float Bs[80][17];   // [col][k]

    const int tid = threadIdx.x;
    const int m0 = blockIdx.x * 64;
    const int n0 = blockIdx.y * 80;
    const int k0 = blockIdx.z * 512;

    const int ty = tid >> 4;           // 0..15 -> rows ty*4..+3
    const int tx = tid & 15;           // 0..15 -> cols tx*5..+4

    const int lr = tid >> 2;           // 0..63 (load row)
    const int lk = (tid & 3) * 4;      // 0,4,8,12 (load k quarter)

    float acc[4][5];
#pragma unroll
    for (int i = 0; i < 4; i++)
#pragma unroll
        for (int j = 0; j < 5; j++) acc[i][j] = 0.0f;

    const float* xg  = x + (size_t)(m0 + lr) * D_INNER + k0 + lk;
    const float* wg0 = w + (size_t)(n0 + lr) * D_INNER + k0 + lk;
    const float* wg1 = w + (size_t)(n0 + 64 + lr) * D_INNER + k0 + lk; // valid for tid<64

    float4 pa  = *(const float4*)xg;
    float4 pb0 = *(const float4*)wg0;
    float4 pb1 = make_float4(0.f, 0.f, 0.f, 0.f);
    if (tid < 64) pb1 = *(const float4*)wg1;

    for (int s = 0; s < 32; s++) {
        As[lr][lk + 0] = pa.x;  As[lr][lk + 1] = pa.y;
        As[lr][lk + 2] = pa.z;  As[lr][lk + 3] = pa.w;
        Bs[lr][lk + 0] = pb0.x; Bs[lr][lk + 1] = pb0.y;
        Bs[lr][lk + 2] = pb0.z; Bs[lr][lk + 3] = pb0.w;
        if (tid < 64) {
            Bs[64 + lr][lk + 0] = pb1.x; Bs[64 + lr][lk + 1] = pb1.y;
            Bs[64 + lr][lk + 2] = pb1.z; Bs[64 + lr][lk + 3] = pb1.w;
        }
        __syncthreads();

        if (s + 1 < 32) {
            pa  = *(const float4*)(xg  + (s + 1) * 16);
            pb0 = *(const float4*)(wg0 + (s + 1) * 16);
            if (tid < 64) pb1 = *(const float4*)(wg1 + (s + 1) * 16);
        }

#pragma unroll
        for (int k = 0; k < 16; k++) {
            float a[4], b[5];
#pragma unroll
            for (int i = 0; i < 4; i++) a[i] = As[ty * 4 + i][k];
#pragma unroll
            for (int j = 0; j < 5; j++) b[j] = Bs[tx * 5 + j][k];
#pragma unroll
            for (int i = 0; i < 4; i++)
#pragma unroll
                for (int j = 0; j < 5; j++)
                    acc[i][j] = fmaf(a[i], b[j], acc[i][j]);
        }
        __syncthreads();
    }

    float* outp = g_part + ((size_t)blockIdx.z * NROWS + m0) * XPC + n0;
#pragma unroll
    for (int i = 0; i < 4; i++)
#pragma unroll
        for (int j = 0; j < 5; j++)
            outp[(size_t)(ty * 4 + i) * XPC + tx * 5 + j] = acc[i][j];
}

// =====================================================================
// reduce split-K partials: g_xp = sum_z g_part[z]
// =====================================================================
__global__ void reduce_kernel()
{
    int i = blockIdx.x * blockDim.x + threadIdx.x;
    if (i < NROWS * XPC) {
        float s = 0.0f;
#pragma unroll
        for (int z = 0; z < KSPLIT; z++) s += g_part[(size_t)z * NROWS * XPC + i];
        g_xp[i] = s;
    }
}

// =====================================================================
// GEMM2: g_dt[row][d] = softplus( sum_r g_xp[row][r] * dtw[d][r] + dtb[d] )
// grid (16 Mtiles, 64 Ntiles), 256 threads, Mtile=Ntile=64, K=128, KC=16
// =====================================================================
__global__ __launch_bounds__(256, 1)
void gemm2_kernel(const float* __restrict__ dtw, const float* __restrict__ dtb)
{
    __shared__ float As[64][17];   // [row][k]
    __shared__ float Bs[64][17];   // [col][k]

    const int tid = threadIdx.x;
    const int m0 = blockIdx.x * 64;
    const int n0 = blockIdx.y * 64;
    const int ty = tid >> 4;
    const int tx = tid & 15;
    const int lr = tid >> 2;
    const int lk = (tid & 3) * 4;

    float acc[4][4];
#pragma unroll
    for (int i = 0; i < 4; i++)
#pragma unroll
        for (int j = 0; j < 4; j++) acc[i][j] = 0.0f;

    const float* ag = g_xp + (size_t)(m0 + lr) * XPC + lk;
    const float* bg = dtw + (size_t)(n0 + lr) * DT_RANK + lk;

    float4 pa = *(const float4*)ag;
    float4 pb = *(const float4*)bg;

    for (int s = 0; s < 8; s++) {
        As[lr][lk + 0] = pa.x; As[lr][lk + 1] = pa.y;
        As[lr][lk + 2] = pa.z; As[lr][lk + 3] = pa.w;
        Bs[lr][lk + 0] = pb.x; Bs[lr][lk + 1] = pb.y;
        Bs[lr][lk + 2] = pb.z; Bs[lr][lk + 3] = pb.w;
        __syncthreads();

        if (s + 1 < 8) {
            pa = *(const float4*)(ag + (s + 1) * 16);
            pb = *(const float4*)(bg + (s + 1) * 16);
        }

#pragma unroll
        for (int k = 0; k < 16; k++) {
            float a[4], b[4];
#pragma unroll
            for (int i = 0; i < 4; i++) a[i] = As[ty * 4 + i][k];
#pragma unroll
            for (int j = 0; j < 4; j++) b[j] = Bs[tx * 4 + j][k];
#pragma unroll
            for (int i = 0; i < 4; i++)
#pragma unroll
                for (int j = 0; j < 4; j++)
                    acc[i][j] = fmaf(a[i], b[j], acc[i][j]);
        }
        __syncthreads();
    }

    float bias[4];
#pragma unroll
    for (int j = 0; j < 4; j++) bias[j] = dtb[n0 + tx * 4 + j];

#pragma unroll
    for (int i = 0; i < 4; i++) {
        float4 o;
        o.x = softplusf(acc[i][0] + bias[0]);
        o.y = softplusf(acc[i][1] + bias[1]);
        o.z = softplusf(acc[i][2] + bias[2]);
        o.w = softplusf(acc[i][3] + bias[3]);
        *(float4*)&g_dt[(size_t)(m0 + ty * 4 + i) * D_INNER + n0 + tx * 4] = o;
    }
}

// =====================================================================
// Scan: 256 blocks (2 batches x 128 d-tiles of 32 channels), 128 threads.
// lane = (channel-in-warp 0..7, q 0..3); each lane owns 4 states.
// cp.async double-buffered staging of x/dt/B/C in 64-step tiles.
// =====================================================================
#define LT 64
#define NTILES (SEQLEN / LT)

__global__ __launch_bounds__(128, 4)
void scan_kernel(const float* __restrict__ x, const float* __restrict__ A_log,
                 const float* __restrict__ Dp, float* __restrict__ y)
{
    extern __shared__ float sm[];
    float* xs  = sm;                   // [2][LT][32]  4096 floats
    float* dts = xs + 2 * LT * 32;     // [2][LT][32]  4096
    float* Bsm = dts + 2 * LT * 32;    // [2][LT][16]  2048
    float* Csm = Bsm + 2 * LT * 16;    // [2][LT][16]  2048

    const int tid = threadIdx.x;
    const int b   = blockIdx.x >> 7;
    const int d0  = (blockIdx.x & 127) * 32;
    const int lane = tid & 31;
    const int w    = tid >> 5;
    const int q    = lane & 3;                 // state quarter
    const int cl   = w * 8 + (lane >> 2);      // local channel 0..31
    const int d    = d0 + cl;

    float A2[4];
#pragma unroll
    for (int j = 0; j < 4; j++)
        A2[j] = -__expf(A_log[d * D_STATE + q * 4 + j]) * 1.4426950408889634f;
    const float Dd = Dp[d];

    float h0 = 0.f, h1 = 0.f, h2 = 0.f, h3 = 0.f;

    const float* xg  = x    + (size_t)b * SEQLEN * D_INNER + d0;
    const float* dtg = g_dt + (size_t)b * SEQLEN * D_INNER + d0;
    const float* Bg  = g_xp + (size_t)b * SEQLEN * XPC + DT_RANK;
    const float* Cg  = g_xp + (size_t)b * SEQLEN * XPC + DT_RANK + D_STATE;

    auto load_tile = [&](int t, int buf) {
        const int l0 = t * LT;
        for (int i = tid; i < LT * 8; i += 128) {
            int ll = i >> 3, sg = (i & 7) * 4;
            cp16(&xs [(buf * LT + ll) * 32 + sg], xg  + (size_t)(l0 + ll) * D_INNER + sg);
            cp16(&dts[(buf * LT + ll) * 32 + sg], dtg + (size_t)(l0 + ll) * D_INNER + sg);
        }
        for (int i = tid; i < LT * 4; i += 128) {
            int ll = i >> 2, sg = (i & 3) * 4;
            cp16(&Bsm[(buf * LT + ll) * 16 + sg], Bg + (size_t)(l0 + ll) * XPC + sg);
            cp16(&Csm[(buf * LT + ll) * 16 + sg], Cg + (size_t)(l0 + ll) * XPC + sg);
        }
    };

    load_tile(0, 0);
    cp_commit();

    for (int t = 0; t < NTILES; t++) {
        if (t + 1 < NTILES) {
            load_tile(t + 1, (t + 1) & 1);
            cp_commit();
            cp_wait<1>();
        } else {
            cp_wait<0>();
        }
        __syncthreads();

        const int buf = t & 1;
        const float* xsb = &xs [buf * LT * 32];
        const float* dtb_ = &dts[buf * LT * 32];
        const float* Bb  = &Bsm[buf * LT * 16];
        const float* Cb  = &Csm[buf * LT * 16];

        float* yout = y + ((size_t)b * SEQLEN + t * LT) * D_INNER + d;

#pragma unroll 4
        for (int ll = 0; ll < LT; ll++) {
            float dtv = dtb_[ll * 32 + cl];
            float xv  = xsb [ll * 32 + cl];
            float4 Bv = *(const float4*)&Bb[ll * 16 + q * 4];
            float4 Cv = *(const float4*)&Cb[ll * 16 + q * 4];

            float dtx = dtv * xv;
            float e0 = ex2f(dtv * A2[0]);
            float e1 = ex2f(dtv * A2[1]);
            float e2 = ex2f(dtv * A2[2]);
            float e3 = ex2f(dtv * A2[3]);
            h0 = fmaf(e0, h0, dtx * Bv.x);
            h1 = fmaf(e1, h1, dtx * Bv.y);
            h2 = fmaf(e2, h2, dtx * Bv.z);
            h3 = fmaf(e3, h3, dtx * Bv.w);

            float p = h0 * Cv.x;
            p = fmaf(h1, Cv.y, p);
            p = fmaf(h2, Cv.z, p);
            p = fmaf(h3, Cv.w, p);
            p += __shfl_xor_sync(0xffffffffu, p, 1);
            p += __shfl_xor_sync(0xffffffffu, p, 2);

            if (q == 0) yout[(size_t)ll * D_INNER] = fmaf(Dd, xv, p);
        }
        __syncthreads();
    }
}

// =====================================================================
// launch
// =====================================================================
extern "C" void kernel_launch(void* const* d_in, const int* in_sizes, int n_in,
                              void* d_out, int out_size)
{
    const float* x     = (const float*)d_in[0];  // (2,512,4096)
    const float* A_log = (const float*)d_in[1];  // (4096,16)
    const float* Dp    = (const float*)d_in[2];  // (4096,)
    const float* xpw   = (const float*)d_in[3];  // (160,4096)
    const float* dtw   = (const float*)d_in[4];  // (4096,128)
    const float* dtb   = (const float*)d_in[5];  // (4096,)
    float* y = (float*)d_out;                    // (2,512,4096)

    gemm1_kernel<<<dim3(16, 2, KSPLIT), 256>>>(x, xpw);
    reduce_kernel<<<(NROWS * XPC + 255) / 256, 256>>>();
    gemm2_kernel<<<dim3(16, 64), 256>>>(dtw, dtb);
    scan_kernel<<<256, 128, 49152>>>(x, A_log, Dp, y);
}